// round 1
// baseline (speedup 1.0000x reference)
#include <cuda_runtime.h>
#include <math.h>

// Problem constants
#define BSZ   16
#define LSZ   4096
#define HD    512
#define IND   1024
#define NCM   16
#define NCLS  10
#define TC    128
#define NCHUNK (LSZ / TC)   // 32

// ---------------- scratch (device globals; no allocation allowed) -------------
__device__ float   g_hn[BSZ * LSZ * HD];                  // 128 MB: relu/gemm1 out, then LN'd in place
__device__ float   g_y [BSZ * LSZ * HD];                  // 128 MB: gelu(s4d) output, input to gemm2
__device__ float2  g_state[(long)BSZ * HD * NCHUNK * NCM]; // 32 MB: chunk states / prefixes
__device__ unsigned g_pool[BSZ * HD];                     // max-pool keys

// monotonic float<->uint key for atomicMax on floats
__device__ __forceinline__ unsigned kencode(float f) {
    unsigned u = __float_as_uint(f);
    return (u & 0x80000000u) ? ~u : (u | 0x80000000u);
}
__device__ __forceinline__ float kdecode(unsigned k) {
    unsigned u = (k & 0x80000000u) ? (k ^ 0x80000000u) : ~k;
    return __uint_as_float(u);
}

// ---------------- init pooled maxes ----------------
__global__ void k_init_pool() {
    int t = blockIdx.x * 256 + threadIdx.x;
    if (t < BSZ * HD) g_pool[t] = 0u;   // key(0)=0 is below every real float key
}

// ---------------- GEMM1: h = relu(x @ fc1_w + b)  (M=65536,K=1024,N=512) -----
__global__ __launch_bounds__(256) void k_gemm1(const float* __restrict__ A,
                                               const float* __restrict__ W,
                                               const float* __restrict__ bias) {
    const int K = IND, N = HD;
    __shared__ float As[2][8][128];
    __shared__ float Bs[2][8][128];
    int tid  = threadIdx.x;
    int row0 = blockIdx.y * 128, col0 = blockIdx.x * 128;
    int a_row = tid >> 1, a_k = (tid & 1) * 4;
    int b_r   = tid >> 5, b_c = (tid & 31) * 4;
    int tx = tid & 15, ty = tid >> 4;

    float acc[8][8];
#pragma unroll
    for (int i = 0; i < 8; i++)
#pragma unroll
        for (int j = 0; j < 8; j++) acc[i][j] = 0.f;

    const float* Aptr = A + (long)(row0 + a_row) * K + a_k;
    float4 av = *(const float4*)Aptr;
    float4 bv = *(const float4*)(W + (long)b_r * N + col0 + b_c);
    As[0][a_k + 0][a_row] = av.x; As[0][a_k + 1][a_row] = av.y;
    As[0][a_k + 2][a_row] = av.z; As[0][a_k + 3][a_row] = av.w;
    *(float4*)&Bs[0][b_r][b_c] = bv;
    __syncthreads();

    const int nt = K / 8;
    for (int kt = 0; kt < nt; ++kt) {
        int buf = kt & 1;
        float4 av2, bv2;
        if (kt + 1 < nt) {
            av2 = *(const float4*)(Aptr + (kt + 1) * 8);
            bv2 = *(const float4*)(W + (long)((kt + 1) * 8 + b_r) * N + col0 + b_c);
        }
#pragma unroll
        for (int kk = 0; kk < 8; kk++) {
            float ar[8], br[8];
#pragma unroll
            for (int i = 0; i < 8; i++) ar[i] = As[buf][kk][ty * 8 + i];
#pragma unroll
            for (int j = 0; j < 8; j++) br[j] = Bs[buf][kk][tx * 8 + j];
#pragma unroll
            for (int i = 0; i < 8; i++)
#pragma unroll
                for (int j = 0; j < 8; j++) acc[i][j] = fmaf(ar[i], br[j], acc[i][j]);
        }
        if (kt + 1 < nt) {
            int nb = buf ^ 1;
            As[nb][a_k + 0][a_row] = av2.x; As[nb][a_k + 1][a_row] = av2.y;
            As[nb][a_k + 2][a_row] = av2.z; As[nb][a_k + 3][a_row] = av2.w;
            *(float4*)&Bs[nb][b_r][b_c] = bv2;
            __syncthreads();
        }
    }
#pragma unroll
    for (int i = 0; i < 8; i++) {
        long r = row0 + ty * 8 + i;
#pragma unroll
        for (int j = 0; j < 8; j += 4) {
            int c = col0 + tx * 8 + j;
            float4 v;
            v.x = fmaxf(acc[i][j + 0] + bias[c + 0], 0.f);
            v.y = fmaxf(acc[i][j + 1] + bias[c + 1], 0.f);
            v.z = fmaxf(acc[i][j + 2] + bias[c + 2], 0.f);
            v.w = fmaxf(acc[i][j + 3] + bias[c + 3], 0.f);
            *(float4*)(g_hn + r * HD + c) = v;
        }
    }
}

// ---------------- LayerNorm in place on g_hn (rows of 512) ----------------
__global__ __launch_bounds__(128) void k_ln(const float* __restrict__ gam,
                                            const float* __restrict__ bet) {
    int row = blockIdx.x, tid = threadIdx.x;
    float* rp = g_hn + (long)row * HD;
    float4 v = *(float4*)(rp + tid * 4);
    float s = v.x + v.y + v.z + v.w;
    float q = v.x * v.x + v.y * v.y + v.z * v.z + v.w * v.w;
#pragma unroll
    for (int o = 16; o > 0; o >>= 1) {
        s += __shfl_xor_sync(0xffffffffu, s, o);
        q += __shfl_xor_sync(0xffffffffu, q, o);
    }
    __shared__ float s1[4], s2[4];
    int w = tid >> 5;
    if ((tid & 31) == 0) { s1[w] = s; s2[w] = q; }
    __syncthreads();
    s = s1[0] + s1[1] + s1[2] + s1[3];
    q = s2[0] + s2[1] + s2[2] + s2[3];
    float mu   = s * (1.f / HD);
    float var  = q * (1.f / HD) - mu * mu;
    float rstd = rsqrtf(var + 1e-5f);
    float4 gv = *(const float4*)(gam + tid * 4);
    float4 bv = *(const float4*)(bet + tid * 4);
    v.x = (v.x - mu) * rstd * gv.x + bv.x;
    v.y = (v.y - mu) * rstd * gv.y + bv.y;
    v.z = (v.z - mu) * rstd * gv.z + bv.z;
    v.w = (v.w - mu) * rstd * gv.w + bv.w;
    *(float4*)(rp + tid * 4) = v;
}

// ---------------- S4D scan phase 1: local chunk end-states -----------------
__global__ __launch_bounds__(256) void k_scan1(const float* __restrict__ log_dt,
                                               const float* __restrict__ A_re,
                                               const float* __restrict__ A_im) {
    int wid  = blockIdx.x * 8 + (threadIdx.x >> 5);
    int lane = threadIdx.x & 31;
    int hg = wid & 15;
    int c  = (wid >> 4) & 31;
    int b  = wid >> 9;
    int h  = hg * 32 + lane;

    float dt = expf(log_dt[h]);
    float wre[NCM], wim[NCM], sre[NCM], sim[NCM];
#pragma unroll
    for (int n = 0; n < NCM; n++) {
        float are = -expf(A_re[h * NCM + n]);
        float aim = A_im[h * NCM + n];
        float er  = expf(are * dt);
        float ph  = aim * dt;
        wre[n] = er * cosf(ph);
        wim[n] = er * sinf(ph);
        sre[n] = 0.f; sim[n] = 0.f;
    }
    const float* up = g_hn + ((long)b * LSZ + (long)c * TC) * HD + h;
    for (int l = 0; l < TC; l++) {
        float uv = up[(long)l * HD];
#pragma unroll
        for (int n = 0; n < NCM; n++) {
            float pr = sre[n], pi = sim[n];
            sre[n] = fmaf(wre[n], pr, fmaf(-wim[n], pi, uv));
            sim[n] = fmaf(wre[n], pi, wim[n] * pr);
        }
    }
    long base = (((long)b * HD + h) * NCHUNK + c) * NCM;
#pragma unroll
    for (int n = 0; n < NCM; n++) g_state[base + n] = make_float2(sre[n], sim[n]);
}

// ---------------- S4D scan phase 2: cross-chunk exclusive prefix -----------
__global__ __launch_bounds__(256) void k_scan2(const float* __restrict__ log_dt,
                                               const float* __restrict__ A_re,
                                               const float* __restrict__ A_im) {
    int t = blockIdx.x * 256 + threadIdx.x;   // BSZ*HD*NCM = 131072 threads
    int n = t & 15;
    int h = (t >> 4) & 511;
    int b = t >> 13;
    double dt  = exp((double)log_dt[h]);
    double are = -exp((double)A_re[h * NCM + n]);
    double aim = (double)A_im[h * NCM + n];
    double drP = are * dt * (double)TC, diP = aim * dt * (double)TC;
    double er  = exp(drP);
    float wtr = (float)(er * cos(diP));
    float wti = (float)(er * sin(diP));
    long base = (((long)b * HD + h) * NCHUNK) * NCM + n;
    float pr = 0.f, pi = 0.f;
    for (int c = 0; c < NCHUNK; c++) {
        float2 e = g_state[base + (long)c * NCM];
        g_state[base + (long)c * NCM] = make_float2(pr, pi);
        float nr = fmaf(wtr, pr, fmaf(-wti, pi, e.x));
        float ni = fmaf(wtr, pi, fmaf(wti, pr, e.y));
        pr = nr; pi = ni;
    }
}

// -------- S4D scan phase 3: rescan with carry, emit gelu(y + u*Dp) ---------
__global__ __launch_bounds__(256) void k_scan3(const float* __restrict__ log_dt,
                                               const float* __restrict__ A_re,
                                               const float* __restrict__ A_im,
                                               const float* __restrict__ C_re,
                                               const float* __restrict__ C_im,
                                               const float* __restrict__ Dp) {
    int wid  = blockIdx.x * 8 + (threadIdx.x >> 5);
    int lane = threadIdx.x & 31;
    int hg = wid & 15;
    int c  = (wid >> 4) & 31;
    int b  = wid >> 9;
    int h  = hg * 32 + lane;

    float dt = expf(log_dt[h]);
    long base = (((long)b * HD + h) * NCHUNK + c) * NCM;
    float wre[NCM], wim[NCM], ckr[NCM], cki[NCM], sre[NCM], sim[NCM];
#pragma unroll
    for (int n = 0; n < NCM; n++) {
        float are = -expf(A_re[h * NCM + n]);
        float aim = A_im[h * NCM + n];
        float er  = expf(are * dt);
        float ph  = aim * dt;
        wre[n] = er * cosf(ph);
        wim[n] = er * sinf(ph);
        // Ck = (C_re + i C_im) * (w - 1) / A ; fold factor 2 in
        float nre = wre[n] - 1.f, nim = wim[n];
        float den = are * are + aim * aim;
        float qre = (nre * are + nim * aim) / den;
        float qim = (nim * are - nre * aim) / den;
        float cr = C_re[h * NCM + n], ci = C_im[h * NCM + n];
        ckr[n] = 2.f * (cr * qre - ci * qim);
        cki[n] = 2.f * (cr * qim + ci * qre);
        float2 s0 = g_state[base + n];
        sre[n] = s0.x; sim[n] = s0.y;
    }
    float dp = Dp[h];
    const float* up = g_hn + ((long)b * LSZ + (long)c * TC) * HD + h;
    float*       yp = g_y  + ((long)b * LSZ + (long)c * TC) * HD + h;
    for (int l = 0; l < TC; l++) {
        float uv = up[(long)l * HD];
        float accv = 0.f;
#pragma unroll
        for (int n = 0; n < NCM; n++) {
            float pr = sre[n], pi = sim[n];
            sre[n] = fmaf(wre[n], pr, fmaf(-wim[n], pi, uv));
            sim[n] = fmaf(wre[n], pi, wim[n] * pr);
            accv = fmaf(ckr[n], sre[n], fmaf(-cki[n], sim[n], accv));
        }
        float yv  = fmaf(uv, dp, accv);
        float gel = 0.5f * yv * (1.f + erff(yv * 0.70710678118654752f));
        yp[(long)l * HD] = gel;
    }
}

// ------- GEMM2 (1x1 conv) + GLU + maxpool fused (M=65536,K=512,Ngated=512) --
__global__ __launch_bounds__(256) void k_gemm2(const float* __restrict__ Wc,
                                               const float* __restrict__ bc) {
    const int K = HD;   // 512
    __shared__ float As[2][8][128];
    __shared__ float Bs[2][8][128];
    __shared__ float red[16][64];
    int tid  = threadIdx.x;
    int row0 = blockIdx.y * 128;
    int jblk = blockIdx.x;            // 0..7, 64 gated channels each
    int a_row = tid >> 1, a_k = (tid & 1) * 4;
    int cc    = tid >> 1, kk0 = (tid & 1) * 4;   // cc in [0,128): interleaved a/b halves
    int tx = tid & 15, ty = tid >> 4;

    // column cc -> output channel: even cc = a-half, odd cc = b-half (+512)
    int o_ld = jblk * 64 + (cc >> 1) + (cc & 1) * 512;
    const float* Aptr = g_y + (long)(row0 + a_row) * K + a_k;
    const float* Bptr = Wc + (long)o_ld * K + kk0;

    float acc[8][8];
#pragma unroll
    for (int i = 0; i < 8; i++)
#pragma unroll
        for (int j = 0; j < 8; j++) acc[i][j] = 0.f;

    float4 av = *(const float4*)Aptr;
    float4 bv = *(const float4*)Bptr;
    As[0][a_k + 0][a_row] = av.x; As[0][a_k + 1][a_row] = av.y;
    As[0][a_k + 2][a_row] = av.z; As[0][a_k + 3][a_row] = av.w;
    Bs[0][kk0 + 0][cc] = bv.x; Bs[0][kk0 + 1][cc] = bv.y;
    Bs[0][kk0 + 2][cc] = bv.z; Bs[0][kk0 + 3][cc] = bv.w;
    __syncthreads();

    const int nt = K / 8;   // 64
    for (int kt = 0; kt < nt; ++kt) {
        int buf = kt & 1;
        float4 av2, bv2;
        if (kt + 1 < nt) {
            av2 = *(const float4*)(Aptr + (kt + 1) * 8);
            bv2 = *(const float4*)(Bptr + (kt + 1) * 8);
        }
#pragma unroll
        for (int kk = 0; kk < 8; kk++) {
            float ar[8], br[8];
#pragma unroll
            for (int i = 0; i < 8; i++) ar[i] = As[buf][kk][ty * 8 + i];
#pragma unroll
            for (int j = 0; j < 8; j++) br[j] = Bs[buf][kk][tx * 8 + j];
#pragma unroll
            for (int i = 0; i < 8; i++)
#pragma unroll
                for (int j = 0; j < 8; j++) acc[i][j] = fmaf(ar[i], br[j], acc[i][j]);
        }
        if (kt + 1 < nt) {
            int nb = buf ^ 1;
            As[nb][a_k + 0][a_row] = av2.x; As[nb][a_k + 1][a_row] = av2.y;
            As[nb][a_k + 2][a_row] = av2.z; As[nb][a_k + 3][a_row] = av2.w;
            Bs[nb][kk0 + 0][cc] = bv2.x; Bs[nb][kk0 + 1][cc] = bv2.y;
            Bs[nb][kk0 + 2][cc] = bv2.z; Bs[nb][kk0 + 3][cc] = bv2.w;
            __syncthreads();
        }
    }

    // fused GLU + intra-block maxpool
    int bidx = row0 >> 12;   // row0 / 4096 : all 128 rows share the same batch b
#pragma unroll
    for (int p = 0; p < 4; p++) {
        int o = jblk * 64 + tx * 4 + p;
        float ba = bc[o], bb = bc[o + 512];
        float m = -3.402823466e38f;
#pragma unroll
        for (int i = 0; i < 8; i++) {
            float a  = acc[i][2 * p]     + ba;
            float bz = acc[i][2 * p + 1] + bb;
            float gv = a * (1.f / (1.f + expf(-bz)));
            m = fmaxf(m, gv);
        }
        red[ty][tx * 4 + p] = m;
    }
    __syncthreads();
    if (ty == 0) {
#pragma unroll
        for (int p = 0; p < 4; p++) {
            float m = red[0][tx * 4 + p];
#pragma unroll
            for (int t = 1; t < 16; t++) m = fmaxf(m, red[t][tx * 4 + p]);
            atomicMax(&g_pool[bidx * HD + jblk * 64 + tx * 4 + p], kencode(m));
        }
    }
}

// ---------------- fc2: logits = pooled @ fc2_w + fc2_b ----------------
__global__ __launch_bounds__(512) void k_fc2(const float* __restrict__ w2,
                                             const float* __restrict__ b2,
                                             float* __restrict__ out) {
    int b = blockIdx.x, tid = threadIdx.x;
    __shared__ float sp[HD];
    sp[tid] = kdecode(g_pool[b * HD + tid]);
    __syncthreads();
    if (tid < NCLS) {
        float s = b2[tid];
        for (int hh = 0; hh < HD; hh++) s = fmaf(sp[hh], w2[hh * NCLS + tid], s);
        out[b * NCLS + tid] = s;
    }
}

// ---------------- launch ----------------
extern "C" void kernel_launch(void* const* d_in, const int* in_sizes, int n_in,
                              void* d_out, int out_size) {
    const float* x      = (const float*)d_in[0];
    const float* fc1_w  = (const float*)d_in[1];
    const float* fc1_b  = (const float*)d_in[2];
    const float* ln_g   = (const float*)d_in[3];
    const float* ln_b   = (const float*)d_in[4];
    const float* log_dt = (const float*)d_in[5];
    const float* A_re   = (const float*)d_in[6];
    const float* A_im   = (const float*)d_in[7];
    const float* C_re   = (const float*)d_in[8];
    const float* C_im   = (const float*)d_in[9];
    const float* Dp     = (const float*)d_in[10];
    const float* conv_w = (const float*)d_in[11];
    const float* conv_b = (const float*)d_in[12];
    const float* fc2_w  = (const float*)d_in[13];
    const float* fc2_b  = (const float*)d_in[14];
    float* out = (float*)d_out;

    k_init_pool<<<32, 256>>>();
    k_gemm1<<<dim3(4, 512), 256>>>(x, fc1_w, fc1_b);
    k_ln<<<BSZ * LSZ, 128>>>(ln_g, ln_b);
    k_scan1<<<1024, 256>>>(log_dt, A_re, A_im);
    k_scan2<<<512, 256>>>(log_dt, A_re, A_im);
    k_scan3<<<1024, 256>>>(log_dt, A_re, A_im, C_re, C_im, Dp);
    k_gemm2<<<dim3(8, 512), 256>>>(conv_w, conv_b);
    k_fc2<<<BSZ, 512>>>(fc2_w, fc2_b, out);
}

// round 3
// speedup vs baseline: 2.2659x; 2.2659x over previous
#include <cuda_runtime.h>
#include <math.h>

// Problem constants
#define BSZ   16
#define LSZ   4096
#define HD    512
#define IND   1024
#define NCM   16
#define NCLS  10
#define TC    128
#define NCHUNK (LSZ / TC)   // 32

// ---------------- scratch (device globals; no allocation allowed) -------------
__device__ float   g_hn[BSZ * LSZ * HD];                  // 128 MB
__device__ float   g_y [BSZ * LSZ * HD];                  // 128 MB
__device__ float2  g_state[(long)BSZ * HD * NCHUNK * NCM]; // 32 MB
__device__ unsigned g_pool[BSZ * HD];

__device__ __forceinline__ unsigned kencode(float f) {
    unsigned u = __float_as_uint(f);
    return (u & 0x80000000u) ? ~u : (u | 0x80000000u);
}
__device__ __forceinline__ float kdecode(unsigned k) {
    unsigned u = (k & 0x80000000u) ? (k ^ 0x80000000u) : ~k;
    return __uint_as_float(u);
}

__device__ __forceinline__ unsigned tf32r(float f) {
    unsigned r;
    asm("cvt.rna.tf32.f32 %0, %1;" : "=r"(r) : "f"(f));
    return r;
}

#define CPA16(dst, src) asm volatile("cp.async.cg.shared.global [%0], [%1], 16;" :: "r"(dst), "l"(src))
#define CPCOMMIT()      asm volatile("cp.async.commit_group;")
#define CPWAIT(n)       asm volatile("cp.async.wait_group %0;" :: "n"(n))

#define MMA8(c, a0, a1, a2, a3, b0, b1)                                             \
    asm volatile("mma.sync.aligned.m16n8k8.row.col.f32.tf32.tf32.f32 "              \
                 "{%0,%1,%2,%3},{%4,%5,%6,%7},{%8,%9},{%0,%1,%2,%3};"               \
                 : "+f"((c)[0]), "+f"((c)[1]), "+f"((c)[2]), "+f"((c)[3])           \
                 : "r"(a0), "r"(a1), "r"(a2), "r"(a3), "r"(b0), "r"(b1))

#define BK   16
#define BKP  20    // BK + 4 pad -> conflict-free (stride-20) pattern
#define BNP  136   // 128 + 8 pad -> conflict-free (8*tig+g) pattern

// ---------------- init pooled maxes ----------------
__global__ void k_init_pool() {
    int t = blockIdx.x * 256 + threadIdx.x;
    if (t < BSZ * HD) g_pool[t] = 0u;
}

// ---------------- GEMM1 (TF32 TC): h = relu(x @ fc1_w + b) -----------------
__global__ __launch_bounds__(256) void k_gemm1(const float* __restrict__ A,
                                               const float* __restrict__ W,
                                               const float* __restrict__ bias) {
    const int K = IND, N = HD;
    __shared__ float As[2][128][BKP];   // [m][k]
    __shared__ float Bs[2][BK][BNP];    // [k][n]
    int tid = threadIdx.x;
    int row0 = blockIdx.y * 128, col0 = blockIdx.x * 128;
    int wid = tid >> 5, lane = tid & 31, g = lane >> 2, tig = lane & 3;
    int wm = wid & 1, wn = wid >> 1;    // warp tile 64x32

    float c[4][4][4];
#pragma unroll
    for (int mt = 0; mt < 4; mt++)
#pragma unroll
        for (int nt = 0; nt < 4; nt++)
#pragma unroll
            for (int q = 0; q < 4; q++) c[mt][nt][q] = 0.f;

#define LOAD_A1(buf, kt)                                                          \
    {                                                                             \
        _Pragma("unroll")                                                         \
        for (int i = 0; i < 2; i++) {                                             \
            int slot = tid + i * 256;                                             \
            int r = slot >> 2, k = (slot & 3) * 4;                                \
            unsigned dst = (unsigned)__cvta_generic_to_shared(&As[buf][r][k]);    \
            CPA16(dst, A + (long)(row0 + r) * K + (kt) * BK + k);                 \
        }                                                                         \
    }
#define LOAD_B1(buf, kt)                                                          \
    {                                                                             \
        _Pragma("unroll")                                                         \
        for (int i = 0; i < 2; i++) {                                             \
            int slot = tid + i * 256;                                             \
            int k = slot >> 5, n = (slot & 31) * 4;                               \
            unsigned dst = (unsigned)__cvta_generic_to_shared(&Bs[buf][k][n]);    \
            CPA16(dst, W + (long)((kt) * BK + k) * N + col0 + n);                 \
        }                                                                         \
    }

    LOAD_A1(0, 0); LOAD_B1(0, 0); CPCOMMIT();
    const int NT = K / BK;   // 64
    for (int kt = 0; kt < NT; kt++) {
        int buf = kt & 1;
        if (kt + 1 < NT) {
            LOAD_A1(buf ^ 1, kt + 1); LOAD_B1(buf ^ 1, kt + 1); CPCOMMIT();
            CPWAIT(1);
        } else {
            CPWAIT(0);
        }
        __syncthreads();
#pragma unroll
        for (int ks = 0; ks < 2; ks++) {
            int kb = ks * 8;
            unsigned af[4][4], bf[4][2];
#pragma unroll
            for (int mt = 0; mt < 4; mt++) {
                int mr = wm * 64 + mt * 16;
                af[mt][0] = tf32r(As[buf][mr + g][kb + tig]);
                af[mt][1] = tf32r(As[buf][mr + g + 8][kb + tig]);
                af[mt][2] = tf32r(As[buf][mr + g][kb + tig + 4]);
                af[mt][3] = tf32r(As[buf][mr + g + 8][kb + tig + 4]);
            }
#pragma unroll
            for (int nt = 0; nt < 4; nt++) {
                int nc = wn * 32 + nt * 8;
                bf[nt][0] = tf32r(Bs[buf][kb + tig][nc + g]);
                bf[nt][1] = tf32r(Bs[buf][kb + tig + 4][nc + g]);
            }
#pragma unroll
            for (int mt = 0; mt < 4; mt++)
#pragma unroll
                for (int nt = 0; nt < 4; nt++)
                    MMA8(c[mt][nt], af[mt][0], af[mt][1], af[mt][2], af[mt][3],
                         bf[nt][0], bf[nt][1]);
        }
        __syncthreads();
    }

#pragma unroll
    for (int mt = 0; mt < 4; mt++) {
        int mr = row0 + wm * 64 + mt * 16;
#pragma unroll
        for (int nt = 0; nt < 4; nt++) {
            int nc = col0 + wn * 32 + nt * 8 + tig * 2;
            float b0v = bias[nc], b1v = bias[nc + 1];
            float2 v0, v1;
            v0.x = fmaxf(c[mt][nt][0] + b0v, 0.f);
            v0.y = fmaxf(c[mt][nt][1] + b1v, 0.f);
            v1.x = fmaxf(c[mt][nt][2] + b0v, 0.f);
            v1.y = fmaxf(c[mt][nt][3] + b1v, 0.f);
            *(float2*)(g_hn + (long)(mr + g) * HD + nc)     = v0;
            *(float2*)(g_hn + (long)(mr + g + 8) * HD + nc) = v1;
        }
    }
}

// ---------------- LayerNorm in place on g_hn (rows of 512) ----------------
__global__ __launch_bounds__(128) void k_ln(const float* __restrict__ gam,
                                            const float* __restrict__ bet) {
    int row = blockIdx.x, tid = threadIdx.x;
    float* rp = g_hn + (long)row * HD;
    float4 v = *(float4*)(rp + tid * 4);
    float s = v.x + v.y + v.z + v.w;
    float q = v.x * v.x + v.y * v.y + v.z * v.z + v.w * v.w;
#pragma unroll
    for (int o = 16; o > 0; o >>= 1) {
        s += __shfl_xor_sync(0xffffffffu, s, o);
        q += __shfl_xor_sync(0xffffffffu, q, o);
    }
    __shared__ float s1[4], s2[4];
    int w = tid >> 5;
    if ((tid & 31) == 0) { s1[w] = s; s2[w] = q; }
    __syncthreads();
    s = s1[0] + s1[1] + s1[2] + s1[3];
    q = s2[0] + s2[1] + s2[2] + s2[3];
    float mu   = s * (1.f / HD);
    float var  = q * (1.f / HD) - mu * mu;
    float rstd = rsqrtf(var + 1e-5f);
    float4 gv = *(const float4*)(gam + tid * 4);
    float4 bv = *(const float4*)(bet + tid * 4);
    v.x = (v.x - mu) * rstd * gv.x + bv.x;
    v.y = (v.y - mu) * rstd * gv.y + bv.y;
    v.z = (v.z - mu) * rstd * gv.z + bv.z;
    v.w = (v.w - mu) * rstd * gv.w + bv.w;
    *(float4*)(rp + tid * 4) = v;
}

// ---------------- S4D scan phase 1: local chunk end-states -----------------
__global__ __launch_bounds__(256) void k_scan1(const float* __restrict__ log_dt,
                                               const float* __restrict__ A_re,
                                               const float* __restrict__ A_im) {
    int wid  = blockIdx.x * 8 + (threadIdx.x >> 5);
    int lane = threadIdx.x & 31;
    int hg = wid & 15;
    int c  = (wid >> 4) & 31;
    int b  = wid >> 9;
    int h  = hg * 32 + lane;

    float dt = expf(log_dt[h]);
    float wre[NCM], wim[NCM], sre[NCM], sim[NCM];
#pragma unroll
    for (int n = 0; n < NCM; n++) {
        float are = -expf(A_re[h * NCM + n]);
        float aim = A_im[h * NCM + n];
        float er  = expf(are * dt);
        float ph  = aim * dt;
        wre[n] = er * cosf(ph);
        wim[n] = er * sinf(ph);
        sre[n] = 0.f; sim[n] = 0.f;
    }
    const float* up = g_hn + ((long)b * LSZ + (long)c * TC) * HD + h;
    for (int l = 0; l < TC; l++) {
        float uv = up[(long)l * HD];
#pragma unroll
        for (int n = 0; n < NCM; n++) {
            float pr = sre[n], pi = sim[n];
            sre[n] = fmaf(wre[n], pr, fmaf(-wim[n], pi, uv));
            sim[n] = fmaf(wre[n], pi, wim[n] * pr);
        }
    }
    long base = (((long)b * HD + h) * NCHUNK + c) * NCM;
#pragma unroll
    for (int n = 0; n < NCM; n++) g_state[base + n] = make_float2(sre[n], sim[n]);
}

// ---------------- S4D scan phase 2: cross-chunk exclusive prefix -----------
__global__ __launch_bounds__(256) void k_scan2(const float* __restrict__ log_dt,
                                               const float* __restrict__ A_re,
                                               const float* __restrict__ A_im) {
    int t = blockIdx.x * 256 + threadIdx.x;
    int n = t & 15;
    int h = (t >> 4) & 511;
    int b = t >> 13;
    double dt  = exp((double)log_dt[h]);
    double are = -exp((double)A_re[h * NCM + n]);
    double aim = (double)A_im[h * NCM + n];
    double drP = are * dt * (double)TC, diP = aim * dt * (double)TC;
    double er  = exp(drP);
    float wtr = (float)(er * cos(diP));
    float wti = (float)(er * sin(diP));
    long base = (((long)b * HD + h) * NCHUNK) * NCM + n;
    float pr = 0.f, pi = 0.f;
    for (int c = 0; c < NCHUNK; c++) {
        float2 e = g_state[base + (long)c * NCM];
        g_state[base + (long)c * NCM] = make_float2(pr, pi);
        float nr = fmaf(wtr, pr, fmaf(-wti, pi, e.x));
        float ni = fmaf(wtr, pi, fmaf(wti, pr, e.y));
        pr = nr; pi = ni;
    }
}

// -------- S4D scan phase 3: rescan with carry, emit gelu(y + u*Dp) ---------
__global__ __launch_bounds__(256) void k_scan3(const float* __restrict__ log_dt,
                                               const float* __restrict__ A_re,
                                               const float* __restrict__ A_im,
                                               const float* __restrict__ C_re,
                                               const float* __restrict__ C_im,
                                               const float* __restrict__ Dp) {
    int wid  = blockIdx.x * 8 + (threadIdx.x >> 5);
    int lane = threadIdx.x & 31;
    int hg = wid & 15;
    int c  = (wid >> 4) & 31;
    int b  = wid >> 9;
    int h  = hg * 32 + lane;

    float dt = expf(log_dt[h]);
    long base = (((long)b * HD + h) * NCHUNK + c) * NCM;
    float wre[NCM], wim[NCM], ckr[NCM], cki[NCM], sre[NCM], sim[NCM];
#pragma unroll
    for (int n = 0; n < NCM; n++) {
        float are = -expf(A_re[h * NCM + n]);
        float aim = A_im[h * NCM + n];
        float er  = expf(are * dt);
        float ph  = aim * dt;
        wre[n] = er * cosf(ph);
        wim[n] = er * sinf(ph);
        float nre = wre[n] - 1.f, nim = wim[n];
        float den = are * are + aim * aim;
        float qre = (nre * are + nim * aim) / den;
        float qim = (nim * are - nre * aim) / den;
        float cr = C_re[h * NCM + n], ci = C_im[h * NCM + n];
        ckr[n] = 2.f * (cr * qre - ci * qim);
        cki[n] = 2.f * (cr * qim + ci * qre);
        float2 s0 = g_state[base + n];
        sre[n] = s0.x; sim[n] = s0.y;
    }
    float dp = Dp[h];
    const float* up = g_hn + ((long)b * LSZ + (long)c * TC) * HD + h;
    float*       yp = g_y  + ((long)b * LSZ + (long)c * TC) * HD + h;
    for (int l = 0; l < TC; l++) {
        float uv = up[(long)l * HD];
        float accv = 0.f;
#pragma unroll
        for (int n = 0; n < NCM; n++) {
            float pr = sre[n], pi = sim[n];
            sre[n] = fmaf(wre[n], pr, fmaf(-wim[n], pi, uv));
            sim[n] = fmaf(wre[n], pi, wim[n] * pr);
            accv = fmaf(ckr[n], sre[n], fmaf(-cki[n], sim[n], accv));
        }
        float yv  = fmaf(uv, dp, accv);
        float gel = 0.5f * yv * (1.f + erff(yv * 0.70710678118654752f));
        yp[(long)l * HD] = gel;
    }
}

// ------- GEMM2 (TF32 TC, 1x1 conv) + GLU + maxpool fused -------------------
__global__ __launch_bounds__(256) void k_gemm2(const float* __restrict__ Wc,
                                               const float* __restrict__ bc) {
    const int K = HD;   // 512
    __shared__ float As2[2][128][BKP];   // [m][k]
    __shared__ float Bs2[2][128][BKP];   // [cc][k] (o-major)
    int tid = threadIdx.x;
    int row0 = blockIdx.y * 128;
    int jblk = blockIdx.x;               // 0..7 -> 64 gated channels each
    int wid = tid >> 5, lane = tid & 31, g = lane >> 2, tig = lane & 3;
    int wm = wid & 1, wn = wid >> 1;

    float c[4][4][4];
#pragma unroll
    for (int mt = 0; mt < 4; mt++)
#pragma unroll
        for (int nt = 0; nt < 4; nt++)
#pragma unroll
            for (int q = 0; q < 4; q++) c[mt][nt][q] = 0.f;

#define LOAD_A2(buf, kt)                                                          \
    {                                                                             \
        _Pragma("unroll")                                                         \
        for (int i = 0; i < 2; i++) {                                             \
            int slot = tid + i * 256;                                             \
            int r = slot >> 2, k = (slot & 3) * 4;                                \
            unsigned dst = (unsigned)__cvta_generic_to_shared(&As2[buf][r][k]);   \
            CPA16(dst, g_y + (long)(row0 + r) * K + (kt) * BK + k);               \
        }                                                                         \
    }
#define LOAD_B2(buf, kt)                                                          \
    {                                                                             \
        _Pragma("unroll")                                                         \
        for (int i = 0; i < 2; i++) {                                             \
            int slot = tid + i * 256;                                             \
            int cc = slot >> 2, k = (slot & 3) * 4;                               \
            int och = jblk * 64 + (cc >> 1) + (cc & 1) * 512;                     \
            unsigned dst = (unsigned)__cvta_generic_to_shared(&Bs2[buf][cc][k]);  \
            CPA16(dst, Wc + (long)och * K + (kt) * BK + k);                       \
        }                                                                         \
    }

    LOAD_A2(0, 0); LOAD_B2(0, 0); CPCOMMIT();
    const int NT = K / BK;   // 32
    for (int kt = 0; kt < NT; kt++) {
        int buf = kt & 1;
        if (kt + 1 < NT) {
            LOAD_A2(buf ^ 1, kt + 1); LOAD_B2(buf ^ 1, kt + 1); CPCOMMIT();
            CPWAIT(1);
        } else {
            CPWAIT(0);
        }
        __syncthreads();
#pragma unroll
        for (int ks = 0; ks < 2; ks++) {
            int kb = ks * 8;
            unsigned af[4][4], bf[4][2];
#pragma unroll
            for (int mt = 0; mt < 4; mt++) {
                int mr = wm * 64 + mt * 16;
                af[mt][0] = tf32r(As2[buf][mr + g][kb + tig]);
                af[mt][1] = tf32r(As2[buf][mr + g + 8][kb + tig]);
                af[mt][2] = tf32r(As2[buf][mr + g][kb + tig + 4]);
                af[mt][3] = tf32r(As2[buf][mr + g + 8][kb + tig + 4]);
            }
#pragma unroll
            for (int nt = 0; nt < 4; nt++) {
                int nc = wn * 32 + nt * 8;
                bf[nt][0] = tf32r(Bs2[buf][nc + g][kb + tig]);
                bf[nt][1] = tf32r(Bs2[buf][nc + g][kb + tig + 4]);
            }
#pragma unroll
            for (int mt = 0; mt < 4; mt++)
#pragma unroll
                for (int nt = 0; nt < 4; nt++)
                    MMA8(c[mt][nt], af[mt][0], af[mt][1], af[mt][2], af[mt][3],
                         bf[nt][0], bf[nt][1]);
        }
        __syncthreads();
    }

    // fused GLU + maxpool: thread's (c0,c1)/(c2,c3) are adjacent interleaved
    // columns = one (a,b) gate pair for gated channel ch.
    int bidx = row0 >> 12;
#pragma unroll
    for (int nt = 0; nt < 4; nt++) {
        int ch = wn * 16 + nt * 4 + tig;      // gated channel within block [0,64)
        int o  = jblk * 64 + ch;              // global gated channel [0,512)
        float ba = bc[o], bb = bc[o + 512];
        float m = -3.402823466e38f;
#pragma unroll
        for (int mt = 0; mt < 4; mt++) {
            float a0 = c[mt][nt][0] + ba, b0 = c[mt][nt][1] + bb;
            float a1 = c[mt][nt][2] + ba, b1 = c[mt][nt][3] + bb;
            float g0 = a0 * (1.f / (1.f + expf(-b0)));
            float g1 = a1 * (1.f / (1.f + expf(-b1)));
            m = fmaxf(m, fmaxf(g0, g1));
        }
        // reduce across g (lane bits 2..4)
        m = fmaxf(m, __shfl_xor_sync(0xffffffffu, m, 4));
        m = fmaxf(m, __shfl_xor_sync(0xffffffffu, m, 8));
        m = fmaxf(m, __shfl_xor_sync(0xffffffffu, m, 16));
        if (lane < 4) atomicMax(&g_pool[bidx * HD + o], kencode(m));
    }
}

// ---------------- fc2: logits = pooled @ fc2_w + fc2_b ----------------
__global__ __launch_bounds__(512) void k_fc2(const float* __restrict__ w2,
                                             const float* __restrict__ b2,
                                             float* __restrict__ out) {
    int b = blockIdx.x, tid = threadIdx.x;
    __shared__ float sp[HD];
    sp[tid] = kdecode(g_pool[b * HD + tid]);
    __syncthreads();
    if (tid < NCLS) {
        float s = b2[tid];
        for (int hh = 0; hh < HD; hh++) s = fmaf(sp[hh], w2[hh * NCLS + tid], s);
        out[b * NCLS + tid] = s;
    }
}

// ---------------- launch ----------------
extern "C" void kernel_launch(void* const* d_in, const int* in_sizes, int n_in,
                              void* d_out, int out_size) {
    const float* x      = (const float*)d_in[0];
    const float* fc1_w  = (const float*)d_in[1];
    const float* fc1_b  = (const float*)d_in[2];
    const float* ln_g   = (const float*)d_in[3];
    const float* ln_b   = (const float*)d_in[4];
    const float* log_dt = (const float*)d_in[5];
    const float* A_re   = (const float*)d_in[6];
    const float* A_im   = (const float*)d_in[7];
    const float* C_re   = (const float*)d_in[8];
    const float* C_im   = (const float*)d_in[9];
    const float* Dp     = (const float*)d_in[10];
    const float* conv_w = (const float*)d_in[11];
    const float* conv_b = (const float*)d_in[12];
    const float* fc2_w  = (const float*)d_in[13];
    const float* fc2_b  = (const float*)d_in[14];
    float* out = (float*)d_out;

    k_init_pool<<<32, 256>>>();
    k_gemm1<<<dim3(4, 512), 256>>>(x, fc1_w, fc1_b);
    k_ln<<<BSZ * LSZ, 128>>>(ln_g, ln_b);
    k_scan1<<<1024, 256>>>(log_dt, A_re, A_im);
    k_scan2<<<512, 256>>>(log_dt, A_re, A_im);
    k_scan3<<<1024, 256>>>(log_dt, A_re, A_im, C_re, C_im, Dp);
    k_gemm2<<<dim3(8, 512), 256>>>(conv_w, conv_b);
    k_fc2<<<BSZ, 512>>>(fc2_w, fc2_b, out);
}